// round 10
// baseline (speedup 1.0000x reference)
#include <cuda_runtime.h>
#include <cuda_bf16.h>

// RoPE, single launch, table-free.
// x is [BH, seq, 128]. Block = (TILE_S=8 s-rows x 32 float4-cols) covering
// BH_CHUNK=8 bh slices. Each thread: front-batch 8 streaming loads (8
// independent 2MB-apart coalesced streams, deep MLP), compute its
// loop-invariant cos/sin quadruple (1 exp2f + 2 accurate sincosf) entirely
// under the DRAM latency, then rotate + store all 8. One kernel, no table.

#define D_MODEL   128
#define D_VEC4    32            // D_MODEL/4
#define TILE_S    8             // s-rows per block
#define BH_CHUNK  8             // bh slices per block
#define NTHREADS  256           // TILE_S * D_VEC4
#define MAX_SEQ   8192

__device__ __forceinline__ float4 rope_rot(float4 v, float4 t) {
    float4 o;
    o.x = fmaf(t.x, v.x, -t.y * v.y);
    o.y = fmaf(t.y, v.x,  t.x * v.y);
    o.z = fmaf(t.z, v.z, -t.w * v.w);
    o.w = fmaf(t.w, v.z,  t.z * v.w);
    return o;
}

// token_positions may be serialized int64 or int32. Little-endian int64
// arrays of small positives have zero odd int32 words. Probe words are
// L1/L2-hot after the first warp touches them.
__device__ __forceinline__ bool detect_is64(const void* tok, unsigned int seq) {
    if (seq < 8) return false;
    const int* v32 = (const int*)tok;
    return (__ldg(v32 + 1) == 0 && __ldg(v32 + 3) == 0 &&
            __ldg(v32 + 5) == 0 && __ldg(v32 + 7) == 0);
}

__device__ __forceinline__ long long load_pos(const void* tok, unsigned int s,
                                              bool is64) {
    return is64 ? ((const long long*)tok)[s] : (long long)((const int*)tok)[s];
}

// ---------------------------------------------------------------------------
// Fast path: d=128, seq % TILE_S == 0, bh % BH_CHUNK == 0.
// grid = (bh/BH_CHUNK) * (seq/TILE_S).
// ---------------------------------------------------------------------------
__global__ void __launch_bounds__(NTHREADS)
rope_direct(const float4* __restrict__ x, float4* __restrict__ out,
            const void* __restrict__ tok_pos,
            unsigned int seq, unsigned int sb_count) {
    unsigned int sblk  = blockIdx.x % sb_count;
    unsigned int chunk = blockIdx.x / sb_count;
    unsigned int srow  = threadIdx.x >> 5;       // 0..7
    unsigned int d4    = threadIdx.x & 31;       // 0..31
    unsigned int s     = sblk * TILE_S + srow;

    // ---- front-batch all 8 streaming loads (independent 2MB-apart streams)
    unsigned int stride = seq * D_VEC4;                       // float4s per bh
    unsigned int base   = (chunk * BH_CHUNK * seq + s) * D_VEC4 + d4;

    float4 v0 = __ldcs(x + base);
    float4 v1 = __ldcs(x + base + stride);
    float4 v2 = __ldcs(x + base + 2u * stride);
    float4 v3 = __ldcs(x + base + 3u * stride);
    float4 v4 = __ldcs(x + base + 4u * stride);
    float4 v5 = __ldcs(x + base + 5u * stride);
    float4 v6 = __ldcs(x + base + 6u * stride);
    float4 v7 = __ldcs(x + base + 7u * stride);

    // ---- cos/sin for pairs 2*d4, 2*d4+1 — computed under load latency ----
    const float LOG2_THETA = 13.287712379549449f;   // log2(10000)
    const float RATIO      = 0.86596432336006535f;  // 10000^(-1/64)
    bool is64 = detect_is64(tok_pos, seq);
    float pf = (float)load_pos(tok_pos, s, is64);

    float e0   = (float)(4u * d4) * (1.0f / 128.0f);     // 2*(2*d4)/d
    float ang0 = pf * exp2f(-e0 * LOG2_THETA);
    float ang1 = ang0 * RATIO;                            // exact identity

    float4 t;
    sincosf(ang0, &t.y, &t.x);   // t.x=cos0, t.y=sin0  (accurate path)
    sincosf(ang1, &t.w, &t.z);   // t.z=cos1, t.w=sin1

    // ---- rotate + store ----
    __stcs(out + base,               rope_rot(v0, t));
    __stcs(out + base +      stride, rope_rot(v1, t));
    __stcs(out + base + 2u * stride, rope_rot(v2, t));
    __stcs(out + base + 3u * stride, rope_rot(v3, t));
    __stcs(out + base + 4u * stride, rope_rot(v4, t));
    __stcs(out + base + 5u * stride, rope_rot(v5, t));
    __stcs(out + base + 6u * stride, rope_rot(v6, t));
    __stcs(out + base + 7u * stride, rope_rot(v7, t));
}

// ---------------------------------------------------------------------------
// Fallback (generic shapes): table + streaming kernels.
// ---------------------------------------------------------------------------
__device__ float4 g_tab4[MAX_SEQ * (D_MODEL / 2) / 2];

__global__ void rope_build_table(const void* __restrict__ tok_pos, int seq) {
    int idx = blockIdx.x * blockDim.x + threadIdx.x;
    if (idx >= seq * (D_MODEL / 2)) return;
    int s = idx >> 6;
    int i = idx & (D_MODEL / 2 - 1);
    bool is64 = detect_is64(tok_pos, (unsigned)seq);
    long long p = load_pos(tok_pos, (unsigned)s, is64);
    const float LOG2_THETA = 13.287712379549449f;
    float e   = (float)(2 * i) * (1.0f / (float)D_MODEL);
    float ang = (float)p * exp2f(-e * LOG2_THETA);
    float sn, cs;
    sincosf(ang, &sn, &cs);
    ((float2*)g_tab4)[(size_t)s * (D_MODEL / 2) + i] = make_float2(cs, sn);
}

__global__ void __launch_bounds__(NTHREADS)
rope_apply1(const float4* __restrict__ x, float4* __restrict__ out,
            unsigned int seq, unsigned int n4) {
    unsigned int i = blockIdx.x * blockDim.x + threadIdx.x;
    if (i >= n4) return;
    unsigned int r = i >> 5;
    unsigned int s = r % seq;
    float4 v = __ldcs(x + i);
    float4 t = g_tab4[s * D_VEC4 + (i & (D_VEC4 - 1))];
    __stcs(out + i, rope_rot(v, t));
}

// ---------------------------------------------------------------------------
extern "C" void kernel_launch(void* const* d_in, const int* in_sizes, int n_in,
                              void* d_out, int out_size) {
    const float* x  = (const float*)d_in[0];
    const void*  tp = d_in[1];

    unsigned int n_elem = (unsigned int)in_sizes[0];
    unsigned int seq    = (unsigned int)in_sizes[1];

    unsigned int bh = 0;
    bool fast = false;
    if (seq > 0 && n_elem % (seq * D_MODEL) == 0) {
        bh = n_elem / (seq * D_MODEL);
        fast = (seq % TILE_S == 0) && (bh % BH_CHUNK == 0);
    }

    if (fast) {
        unsigned int sb_count = seq / TILE_S;
        unsigned int grid = sb_count * (bh / BH_CHUNK);
        rope_direct<<<grid, NTHREADS>>>((const float4*)x, (float4*)d_out, tp,
                                        seq, sb_count);
    } else {
        unsigned int su = seq > MAX_SEQ ? MAX_SEQ : seq;
        int total = (int)(su * (D_MODEL / 2));
        rope_build_table<<<(total + 255) / 256, 256>>>(tp, (int)su);
        unsigned int n4 = n_elem / 4;
        rope_apply1<<<(n4 + NTHREADS - 1) / NTHREADS, NTHREADS>>>(
            (const float4*)x, (float4*)d_out, su, n4);
    }
}

// round 11
// speedup vs baseline: 1.0090x; 1.0090x over previous
#include <cuda_runtime.h>
#include <cuda_bf16.h>

// RoPE, single launch, table-free.
// x is [BH, seq, 128]. Block = (TILE_S=4 s-rows x 32 float4-cols) covering
// BH_CHUNK=4 bh slices -> 32768 blocks for the bench shape (finer tail-wave
// granularity than the 16384-block R9 winner, same per-thread structure).
// Each thread: front-batch 4 streaming loads (independent 2MB-apart coalesced
// streams), compute its loop-invariant cos/sin quadruple (1 exp2f + 2
// accurate sincosf) under the DRAM latency, rotate, store. No table, no gap.

#define D_MODEL   128
#define D_VEC4    32            // D_MODEL/4
#define TILE_S    4             // s-rows per block
#define BH_CHUNK  4             // bh slices per block
#define NTHREADS  128           // TILE_S * D_VEC4
#define MAX_SEQ   8192

__device__ __forceinline__ float4 rope_rot(float4 v, float4 t) {
    float4 o;
    o.x = fmaf(t.x, v.x, -t.y * v.y);
    o.y = fmaf(t.y, v.x,  t.x * v.y);
    o.z = fmaf(t.z, v.z, -t.w * v.w);
    o.w = fmaf(t.w, v.z,  t.z * v.w);
    return o;
}

// token_positions may be serialized int64 or int32. Little-endian int64
// arrays of small positives have zero odd int32 words. Probe words are
// L1/L2-hot after the first warp touches them.
__device__ __forceinline__ bool detect_is64(const void* tok, unsigned int seq) {
    if (seq < 8) return false;
    const int* v32 = (const int*)tok;
    return (__ldg(v32 + 1) == 0 && __ldg(v32 + 3) == 0 &&
            __ldg(v32 + 5) == 0 && __ldg(v32 + 7) == 0);
}

__device__ __forceinline__ long long load_pos(const void* tok, unsigned int s,
                                              bool is64) {
    return is64 ? ((const long long*)tok)[s] : (long long)((const int*)tok)[s];
}

// ---------------------------------------------------------------------------
// Fast path: d=128, seq % TILE_S == 0, bh % BH_CHUNK == 0.
// grid = (bh/BH_CHUNK) * (seq/TILE_S); sblk fastest -> consecutive blocks
// sweep contiguous addresses within a bh-group slab.
// ---------------------------------------------------------------------------
__global__ void __launch_bounds__(NTHREADS)
rope_direct(const float4* __restrict__ x, float4* __restrict__ out,
            const void* __restrict__ tok_pos,
            unsigned int seq, unsigned int sb_count) {
    unsigned int sblk  = blockIdx.x % sb_count;
    unsigned int chunk = blockIdx.x / sb_count;
    unsigned int srow  = threadIdx.x >> 5;       // 0..TILE_S-1
    unsigned int d4    = threadIdx.x & 31;       // 0..31
    unsigned int s     = sblk * TILE_S + srow;

    // ---- front-batch the 4 streaming loads (independent 2MB-apart streams)
    unsigned int stride = seq * D_VEC4;                       // float4s per bh
    unsigned int base   = (chunk * BH_CHUNK * seq + s) * D_VEC4 + d4;
    unsigned int i0 = base, i1 = base + stride,
                 i2 = base + 2u * stride, i3 = base + 3u * stride;

    float4 v0 = __ldcs(x + i0);
    float4 v1 = __ldcs(x + i1);
    float4 v2 = __ldcs(x + i2);
    float4 v3 = __ldcs(x + i3);

    // ---- cos/sin for pairs 2*d4, 2*d4+1 — computed under load latency ----
    const float LOG2_THETA = 13.287712379549449f;   // log2(10000)
    const float RATIO      = 0.86596432336006535f;  // 10000^(-1/64)
    bool is64 = detect_is64(tok_pos, seq);
    float pf = (float)load_pos(tok_pos, s, is64);

    float e0   = (float)(4u * d4) * (1.0f / 128.0f);     // 2*(2*d4)/d
    float ang0 = pf * exp2f(-e0 * LOG2_THETA);
    float ang1 = ang0 * RATIO;                            // exact identity

    float4 t;
    sincosf(ang0, &t.y, &t.x);   // t.x=cos0, t.y=sin0  (accurate path)
    sincosf(ang1, &t.w, &t.z);   // t.z=cos1, t.w=sin1

    // ---- rotate + store ----
    __stcs(out + i0, rope_rot(v0, t));
    __stcs(out + i1, rope_rot(v1, t));
    __stcs(out + i2, rope_rot(v2, t));
    __stcs(out + i3, rope_rot(v3, t));
}

// ---------------------------------------------------------------------------
// Fallback (generic shapes): table + streaming kernels.
// ---------------------------------------------------------------------------
__device__ float4 g_tab4[MAX_SEQ * (D_MODEL / 2) / 2];

__global__ void rope_build_table(const void* __restrict__ tok_pos, int seq) {
    int idx = blockIdx.x * blockDim.x + threadIdx.x;
    if (idx >= seq * (D_MODEL / 2)) return;
    int s = idx >> 6;
    int i = idx & (D_MODEL / 2 - 1);
    bool is64 = detect_is64(tok_pos, (unsigned)seq);
    long long p = load_pos(tok_pos, (unsigned)s, is64);
    const float LOG2_THETA = 13.287712379549449f;
    float e   = (float)(2 * i) * (1.0f / (float)D_MODEL);
    float ang = (float)p * exp2f(-e * LOG2_THETA);
    float sn, cs;
    sincosf(ang, &sn, &cs);
    ((float2*)g_tab4)[(size_t)s * (D_MODEL / 2) + i] = make_float2(cs, sn);
}

__global__ void __launch_bounds__(256)
rope_apply1(const float4* __restrict__ x, float4* __restrict__ out,
            unsigned int seq, unsigned int n4) {
    unsigned int i = blockIdx.x * blockDim.x + threadIdx.x;
    if (i >= n4) return;
    unsigned int r = i >> 5;
    unsigned int s = r % seq;
    float4 v = __ldcs(x + i);
    float4 t = g_tab4[s * D_VEC4 + (i & (D_VEC4 - 1))];
    __stcs(out + i, rope_rot(v, t));
}

// ---------------------------------------------------------------------------
extern "C" void kernel_launch(void* const* d_in, const int* in_sizes, int n_in,
                              void* d_out, int out_size) {
    const float* x  = (const float*)d_in[0];
    const void*  tp = d_in[1];

    unsigned int n_elem = (unsigned int)in_sizes[0];
    unsigned int seq    = (unsigned int)in_sizes[1];

    unsigned int bh = 0;
    bool fast = false;
    if (seq > 0 && n_elem % (seq * D_MODEL) == 0) {
        bh = n_elem / (seq * D_MODEL);
        fast = (seq % TILE_S == 0) && (bh % BH_CHUNK == 0);
    }

    if (fast) {
        unsigned int sb_count = seq / TILE_S;
        unsigned int grid = sb_count * (bh / BH_CHUNK);
        rope_direct<<<grid, NTHREADS>>>((const float4*)x, (float4*)d_out, tp,
                                        seq, sb_count);
    } else {
        unsigned int su = seq > MAX_SEQ ? MAX_SEQ : seq;
        int total = (int)(su * (D_MODEL / 2));
        rope_build_table<<<(total + 255) / 256, 256>>>(tp, (int)su);
        unsigned int n4 = n_elem / 4;
        rope_apply1<<<(n4 + 255) / 256, 256>>>(
            (const float4*)x, (float4*)d_out, su, n4);
    }
}

// round 13
// speedup vs baseline: 1.0098x; 1.0008x over previous
#include <cuda_runtime.h>
#include <cuda_bf16.h>

// RoPE, single launch, table-free, fast trig.
// x is [BH, seq, 128]. Block = (TILE_S=8 s-rows x 32 float4-cols) covering
// BH_CHUNK=4 bh slices -> 16384 blocks (R9's best-measured memory shape).
// Per thread: front-batch 4 streaming loads (independent 2MB-apart coalesced
// streams), then compute the loop-invariant cos/sin quadruple with exact
// FP32 Cody-Waite range reduction + MUFU sin/cos approx (|r|<=pi where the
// HW approx is ~7e-7 accurate), rotate, store. Trig chain ~14 ops instead of
// ~150 FMAs of accurate sincosf -> issue pressure matches the table kernel.

#define D_MODEL   128
#define D_VEC4    32            // D_MODEL/4
#define TILE_S    8             // s-rows per block
#define BH_CHUNK  4             // bh slices per block
#define NTHREADS  256           // TILE_S * D_VEC4
#define MAX_SEQ   8192

__device__ __forceinline__ float4 rope_rot(float4 v, float4 t) {
    float4 o;
    o.x = fmaf(t.x, v.x, -t.y * v.y);
    o.y = fmaf(t.y, v.x,  t.x * v.y);
    o.z = fmaf(t.z, v.z, -t.w * v.w);
    o.w = fmaf(t.w, v.z,  t.z * v.w);
    return o;
}

// Exact-ish sincos for |ang| up to ~2^15 rad: Cody-Waite two-constant
// reduction (FMA-exact products) + HW approx on the reduced argument.
__device__ __forceinline__ void fast_sincos(float ang, float* sn, float* cs) {
    const float INV_2PI   = 0.15915494309189535f;
    const float TWO_PI_HI = 6.283185482025146484375f;   // float(2*pi)
    const float TWO_PI_LO = -1.7484556000744487e-07f;   // 2*pi - HI (dbl)
    float k = rintf(ang * INV_2PI);
    float r = fmaf(k, -TWO_PI_HI, ang);
    r       = fmaf(k, -TWO_PI_LO, r);
    __sincosf(r, sn, cs);       // MUFU sin/cos approx, |r| <= pi
}

// token_positions may be serialized int64 or int32. Little-endian int64
// arrays of small positives have zero odd int32 words. Probe words are
// L1/L2-hot after the first warp touches them.
__device__ __forceinline__ bool detect_is64(const void* tok, unsigned int seq) {
    if (seq < 8) return false;
    const int* v32 = (const int*)tok;
    return (__ldg(v32 + 1) == 0 && __ldg(v32 + 3) == 0 &&
            __ldg(v32 + 5) == 0 && __ldg(v32 + 7) == 0);
}

__device__ __forceinline__ long long load_pos(const void* tok, unsigned int s,
                                              bool is64) {
    return is64 ? ((const long long*)tok)[s] : (long long)((const int*)tok)[s];
}

// ---------------------------------------------------------------------------
// Fast path: d=128, seq % TILE_S == 0, bh % BH_CHUNK == 0.
// grid = (bh/BH_CHUNK) * (seq/TILE_S).
// ---------------------------------------------------------------------------
__global__ void __launch_bounds__(NTHREADS)
rope_direct(const float4* __restrict__ x, float4* __restrict__ out,
            const void* __restrict__ tok_pos,
            unsigned int seq, unsigned int sb_count) {
    unsigned int sblk  = blockIdx.x % sb_count;
    unsigned int chunk = blockIdx.x / sb_count;
    unsigned int srow  = threadIdx.x >> 5;       // 0..TILE_S-1
    unsigned int d4    = threadIdx.x & 31;       // 0..31
    unsigned int s     = sblk * TILE_S + srow;

    // ---- front-batch the 4 streaming loads (independent 2MB-apart streams)
    unsigned int stride = seq * D_VEC4;                       // float4s per bh
    unsigned int base   = (chunk * BH_CHUNK * seq + s) * D_VEC4 + d4;
    unsigned int i0 = base, i1 = base + stride,
                 i2 = base + 2u * stride, i3 = base + 3u * stride;

    float4 v0 = __ldcs(x + i0);
    float4 v1 = __ldcs(x + i1);
    float4 v2 = __ldcs(x + i2);
    float4 v3 = __ldcs(x + i3);

    // ---- cos/sin for pairs 2*d4, 2*d4+1 — computed under load latency ----
    const float LOG2_THETA = 13.287712379549449f;   // log2(10000)
    const float RATIO      = 0.86596432336006535f;  // 10000^(-1/64)
    bool is64 = detect_is64(tok_pos, seq);
    float pf = (float)load_pos(tok_pos, s, is64);

    float e0   = (float)(4u * d4) * (1.0f / 128.0f);     // 2*(2*d4)/d
    float ang0 = pf * exp2f(-e0 * LOG2_THETA);
    float ang1 = ang0 * RATIO;                            // exact identity

    float4 t;
    fast_sincos(ang0, &t.y, &t.x);   // t.x=cos0, t.y=sin0
    fast_sincos(ang1, &t.w, &t.z);   // t.z=cos1, t.w=sin1

    // ---- rotate + store ----
    __stcs(out + i0, rope_rot(v0, t));
    __stcs(out + i1, rope_rot(v1, t));
    __stcs(out + i2, rope_rot(v2, t));
    __stcs(out + i3, rope_rot(v3, t));
}

// ---------------------------------------------------------------------------
// Fallback (generic shapes): table + streaming kernels (accurate sincosf —
// off the fast path, cost irrelevant).
// ---------------------------------------------------------------------------
__device__ float4 g_tab4[MAX_SEQ * (D_MODEL / 2) / 2];

__global__ void rope_build_table(const void* __restrict__ tok_pos, int seq) {
    int idx = blockIdx.x * blockDim.x + threadIdx.x;
    if (idx >= seq * (D_MODEL / 2)) return;
    int s = idx >> 6;
    int i = idx & (D_MODEL / 2 - 1);
    bool is64 = detect_is64(tok_pos, (unsigned)seq);
    long long p = load_pos(tok_pos, (unsigned)s, is64);
    const float LOG2_THETA = 13.287712379549449f;
    float e   = (float)(2 * i) * (1.0f / (float)D_MODEL);
    float ang = (float)p * exp2f(-e * LOG2_THETA);
    float sn, cs;
    sincosf(ang, &sn, &cs);
    ((float2*)g_tab4)[(size_t)s * (D_MODEL / 2) + i] = make_float2(cs, sn);
}

__global__ void __launch_bounds__(256)
rope_apply1(const float4* __restrict__ x, float4* __restrict__ out,
            unsigned int seq, unsigned int n4) {
    unsigned int i = blockIdx.x * blockDim.x + threadIdx.x;
    if (i >= n4) return;
    unsigned int r = i >> 5;
    unsigned int s = r % seq;
    float4 v = __ldcs(x + i);
    float4 t = g_tab4[s * D_VEC4 + (i & (D_VEC4 - 1))];
    __stcs(out + i, rope_rot(v, t));
}

// ---------------------------------------------------------------------------
extern "C" void kernel_launch(void* const* d_in, const int* in_sizes, int n_in,
                              void* d_out, int out_size) {
    const float* x  = (const float*)d_in[0];
    const void*  tp = d_in[1];

    unsigned int n_elem = (unsigned int)in_sizes[0];
    unsigned int seq    = (unsigned int)in_sizes[1];

    unsigned int bh = 0;
    bool fast = false;
    if (seq > 0 && n_elem % (seq * D_MODEL) == 0) {
        bh = n_elem / (seq * D_MODEL);
        fast = (seq % TILE_S == 0) && (bh % BH_CHUNK == 0);
    }

    if (fast) {
        unsigned int sb_count = seq / TILE_S;
        unsigned int grid = sb_count * (bh / BH_CHUNK);
        rope_direct<<<grid, NTHREADS>>>((const float4*)x, (float4*)d_out, tp,
                                        seq, sb_count);
    } else {
        unsigned int su = seq > MAX_SEQ ? MAX_SEQ : seq;
        int total = (int)(su * (D_MODEL / 2));
        rope_build_table<<<(total + 255) / 256, 256>>>(tp, (int)su);
        unsigned int n4 = n_elem / 4;
        rope_apply1<<<(n4 + 255) / 256, 256>>>(
            (const float4*)x, (float4*)d_out, su, n4);
    }
}